// round 3
// baseline (speedup 1.0000x reference)
#include <cuda_runtime.h>
#include <math.h>

#define NIMG 8
#define AA 3
#define HH 336
#define WW 336
#define HWSZ (HH*WW)            // 112896
#define MM (AA*HWSZ)            // 338688
#define PRE_K 2000
#define POST_N 1000
#define CAND_CAP 4096
#define MASK_ROWS 2048
#define MASK_WORDS 64
#define NEGV (-1e9f)
#define FULLM 0xffffffffu

// ---------------- scratch (device globals; no allocations) ----------------
__device__ float              d_scores[NIMG * MM];                       // 10.8 MB
__device__ unsigned int       d_hist[NIMG * 65536];                      // 2 MB
__device__ int                d_threshbin[NIMG];
__device__ int                d_candcount[NIMG];
__device__ unsigned long long d_cand[NIMG * CAND_CAP];                   // 256 KB
__device__ float4             d_boxes[NIMG * PRE_K];                     // 256 KB
__device__ float              d_selscore[NIMG * PRE_K];
__device__ float              d_area[NIMG * PRE_K];
__device__ unsigned int       d_maskbits[NIMG * MASK_ROWS * MASK_WORDS]; // 4 MB
__device__ unsigned int       d_validmask[NIMG * MASK_WORDS];

// ---------------- K0: zero counters/hist ----------------
__global__ void k0_zero() {
    int t = blockIdx.x * blockDim.x + threadIdx.x;
    if (t < NIMG * 65536) d_hist[t] = 0u;
    if (t < NIMG) d_candcount[t] = 0;
}

// ---------------- K1: sigmoid scores + ordered-float histogram ----------------
__global__ void k1_scores(const float* __restrict__ logits) {
    int t = blockIdx.x * blockDim.x + threadIdx.x;
    if (t >= NIMG * MM) return;
    int n = t / MM;
    int f = t - n * MM;
    int a  = f % AA;
    int hw = f / AA;
    float x = logits[n * MM + a * HWSZ + hw];
    float s = 1.0f / (1.0f + expf(-x));
    d_scores[t] = s;
    unsigned su = __float_as_uint(s);
    unsigned u = (su & 0x80000000u) ? ~su : (su | 0x80000000u);
    atomicAdd(&d_hist[(n << 16) + (u >> 16)], 1u);
}

// ---------------- K2: find per-image threshold bin for rank PRE_K ----------------
__global__ void k2_thresh() {
    int n = blockIdx.x;
    int t = threadIdx.x;  // 256 threads
    __shared__ unsigned csum[256];
    __shared__ unsigned bins[256];
    __shared__ int      s_chunk;
    __shared__ unsigned s_cum;
    const unsigned* h = d_hist + (n << 16);
    unsigned s = 0;
#pragma unroll 8
    for (int b = 0; b < 256; b++) s += h[t * 256 + b];
    csum[t] = s;
    __syncthreads();
    if (t == 0) {
        unsigned cum = 0;
        int chunk = 0;
        for (int c = 255; c >= 0; c--) {
            if (cum + csum[c] >= PRE_K) { chunk = c; break; }
            cum += csum[c];
        }
        s_chunk = chunk;
        s_cum = cum;
    }
    __syncthreads();
    int chunk = s_chunk;
    bins[t] = h[chunk * 256 + t];
    __syncthreads();
    if (t == 0) {
        unsigned cum = s_cum;
        int thresh = chunk * 256;
        for (int b = 255; b >= 0; b--) {
            cum += bins[b];
            if (cum >= PRE_K) { thresh = chunk * 256 + b; break; }
        }
        d_threshbin[n] = thresh;
    }
}

// ---------------- K3: compact candidate keys ----------------
__global__ void k3_compact() {
    int t = blockIdx.x * blockDim.x + threadIdx.x;
    if (t >= NIMG * MM) return;
    int n = t / MM;
    int f = t - n * MM;
    float s = d_scores[t];
    unsigned su = __float_as_uint(s);
    unsigned u = (su & 0x80000000u) ? ~su : (su | 0x80000000u);
    if ((int)(u >> 16) >= d_threshbin[n]) {
        int pos = atomicAdd(&d_candcount[n], 1);
        if (pos < CAND_CAP) {
            d_cand[n * CAND_CAP + pos] =
                ((unsigned long long)u << 32) | (unsigned long long)(0xFFFFFFFFu - (unsigned)f);
        }
    }
}

// ---------------- K4: per-image bitonic sort + decode/clip top-2000 ----------------
__global__ __launch_bounds__(1024) void k4_sortdecode(const float* __restrict__ anchors,
                                                      const float* __restrict__ breg) {
    __shared__ unsigned long long sm[CAND_CAP];
    int n = blockIdx.x;
    int tid = threadIdx.x;  // 1024
    int cnt = d_candcount[n];
    if (cnt > CAND_CAP) cnt = CAND_CAP;
    for (int i = tid; i < CAND_CAP; i += 1024)
        sm[i] = (i < cnt) ? d_cand[n * CAND_CAP + i] : 0ULL;
    __syncthreads();

    // bitonic sort, descending
    for (int k = 2; k <= CAND_CAP; k <<= 1) {
        for (int j = k >> 1; j > 0; j >>= 1) {
#pragma unroll
            for (int t4 = 0; t4 < CAND_CAP / 1024; t4++) {
                int i = tid + t4 * 1024;
                int ixj = i ^ j;
                if (ixj > i) {
                    unsigned long long va = sm[i], vb = sm[ixj];
                    bool desc = ((i & k) == 0);
                    if (desc ? (va < vb) : (va > vb)) { sm[i] = vb; sm[ixj] = va; }
                }
            }
            __syncthreads();
        }
    }

    const float XCLIP = 4.135166556742356f;  // log(1000/16)
#pragma unroll
    for (int pass = 0; pass < 2; pass++) {
        int r = tid + pass * 1024;
        bool keepf = false;
        if (r < PRE_K) {
            unsigned long long key = sm[r];
            unsigned ub = (unsigned)(key >> 32);
            unsigned sbits = (ub & 0x80000000u) ? (ub ^ 0x80000000u) : ~ub;
            float s = __uint_as_float(sbits);
            unsigned f = 0xFFFFFFFFu - (unsigned)(key & 0xFFFFFFFFull);
            int a  = (int)(f % AA);
            int hw = (int)(f / AA);
            float4 anc = ((const float4*)anchors)[(size_t)n * MM + f];
            const float* rp = breg + ((size_t)n * (AA * 4) + a * 4) * HWSZ + hw;
            float dx = rp[0];
            float dy = rp[HWSZ];
            float dwv = rp[2 * HWSZ];
            float dhv = rp[3 * HWSZ];
            float aw = __fadd_rn(__fsub_rn(anc.z, anc.x), 1.0f);
            float ah = __fadd_rn(__fsub_rn(anc.w, anc.y), 1.0f);
            float cx = __fadd_rn(anc.x, __fmul_rn(0.5f, aw));
            float cy = __fadd_rn(anc.y, __fmul_rn(0.5f, ah));
            dwv = fminf(dwv, XCLIP);
            dhv = fminf(dhv, XCLIP);
            float pcx = __fadd_rn(__fmul_rn(dx, aw), cx);
            float pcy = __fadd_rn(__fmul_rn(dy, ah), cy);
            float pw = __fmul_rn((float)exp((double)dwv), aw);
            float ph = __fmul_rn((float)exp((double)dhv), ah);
            float hpw = __fmul_rn(0.5f, pw);
            float hph = __fmul_rn(0.5f, ph);
            float x1 = __fsub_rn(pcx, hpw);
            float y1 = __fsub_rn(pcy, hph);
            float x2 = __fsub_rn(__fadd_rn(pcx, hpw), 1.0f);
            float y2 = __fsub_rn(__fadd_rn(pcy, hph), 1.0f);
            x1 = fminf(fmaxf(x1, 0.0f), 1332.0f);
            x2 = fminf(fmaxf(x2, 0.0f), 1332.0f);
            y1 = fminf(fmaxf(y1, 0.0f), 799.0f);
            y2 = fminf(fmaxf(y2, 0.0f), 799.0f);
            float ws = __fadd_rn(__fsub_rn(x2, x1), 1.0f);
            float hs = __fadd_rn(__fsub_rn(y2, y1), 1.0f);
            keepf = (ws >= 0.0f) && (hs >= 0.0f);
            d_boxes[n * PRE_K + r] = make_float4(x1, y1, x2, y2);
            d_area[n * PRE_K + r] = __fmul_rn(ws, hs);
            d_selscore[n * PRE_K + r] = keepf ? s : NEGV;
        }
        unsigned bal = __ballot_sync(FULLM, keepf);
        if ((tid & 31) == 0) d_validmask[n * MASK_WORDS + (r >> 5)] = bal;
    }
}

// ---------------- K5: 2000x2000 suppression bitmask ----------------
#define RPB 32
__global__ __launch_bounds__(128) void k5_mask() {
    __shared__ float4 sb[PRE_K];
    __shared__ float  sa[PRE_K];
    const int bpi = (PRE_K + RPB - 1) / RPB;  // 63
    int n  = blockIdx.x / bpi;
    int rb = (blockIdx.x % bpi) * RPB;
    int tid = threadIdx.x;  // 128
    for (int i = tid; i < PRE_K; i += 128) {
        sb[i] = d_boxes[n * PRE_K + i];
        sa[i] = d_area[n * PRE_K + i];
    }
    __syncthreads();
    int warp = tid >> 5, lane = tid & 31;
#pragma unroll
    for (int rr = 0; rr < RPB / 4; rr++) {
        int i = rb + warp + rr * 4;
        if (i < PRE_K) {
            float4 bi = sb[i];
            float ai = sa[i];
            unsigned* row = d_maskbits + ((size_t)n * MASK_ROWS + i) * MASK_WORDS;
            for (int w = 0; w < 63; w++) {
                int j = (w << 5) + lane;
                bool sup = false;
                if (j < PRE_K) {
                    float4 bj = sb[j];
                    float xx1 = fmaxf(bi.x, bj.x);
                    float yy1 = fmaxf(bi.y, bj.y);
                    float xx2 = fminf(bi.z, bj.z);
                    float yy2 = fminf(bi.w, bj.w);
                    float iw = fmaxf(__fadd_rn(__fsub_rn(xx2, xx1), 1.0f), 0.0f);
                    float ih = fmaxf(__fadd_rn(__fsub_rn(yy2, yy1), 1.0f), 0.0f);
                    float inter = __fmul_rn(iw, ih);
                    float denom = __fsub_rn(__fadd_rn(ai, sa[j]), inter);
                    float iou = __fdiv_rn(inter, denom);
                    sup = iou > 0.7f;
                }
                unsigned bal = __ballot_sync(FULLM, sup);
                if (lane == 0) row[w] = bal;
            }
            if (lane == 0) row[63] = 0u;
        }
    }
}

// ---------------- K6: serial greedy NMS scan, 1 warp per image ----------------
__device__ __forceinline__ void k6_load_group(const unsigned* __restrict__ maskb, int lane,
                                              int i0, unsigned (&b0)[8], unsigned (&b1)[8]) {
#pragma unroll
    for (int d = 0; d < 8; d++) {
        const unsigned* r = maskb + (size_t)(i0 + d) * MASK_WORDS;
        b0[d] = r[lane];
        b1[d] = r[lane + 32];
    }
}

__device__ __forceinline__ void k6_proc_group(int i0, int lane,
                                              unsigned (&b0)[8], unsigned (&b1)[8],
                                              unsigned& sup0, unsigned& sup1,
                                              unsigned val0, unsigned val1,
                                              int& count, int* list) {
    int Wd = i0 >> 5;             // constant across the 8-row group
    int slot = Wd >> 5;
    int ol = Wd & 31;
    unsigned kb = slot ? sup1 : sup0;
    unsigned kv = slot ? val1 : val0;
    unsigned keep8 = 0;
    int bit0 = i0 & 31;
#pragma unroll
    for (int d = 0; d < 8; d++) {
        unsigned m = 1u << (bit0 + d);
        if ((kv & m) && !(kb & m)) {
            keep8 |= (1u << d);
            kb |= slot ? b1[d] : b0[d];   // owner lane holds word Wd of row i0+d
        }
    }
    keep8 = __shfl_sync(FULLM, keep8, ol);
#pragma unroll
    for (int d = 0; d < 8; d++) {
        if (keep8 & (1u << d)) { sup0 |= b0[d]; sup1 |= b1[d]; }
    }
    if (lane == 0) {
        int c = count;
#pragma unroll
        for (int d = 0; d < 8; d++) {
            if (keep8 & (1u << d)) {
                if (c < POST_N) list[c] = i0 + d;
                c++;
            }
        }
    }
    count += __popc(keep8);
}

__global__ __launch_bounds__(32) void k6_nms(float* __restrict__ out) {
    int n = blockIdx.x;
    int lane = threadIdx.x;
    __shared__ int list[POST_N];
    const unsigned* maskb = d_maskbits + (size_t)n * MASK_ROWS * MASK_WORDS;
    unsigned sup0 = 0, sup1 = 0;
    unsigned val0 = d_validmask[n * MASK_WORDS + lane];
    unsigned val1 = d_validmask[n * MASK_WORDS + 32 + lane];
    int count = 0;
    unsigned A0[8], A1[8], B0[8], B1[8];

    k6_load_group(maskb, lane, 0, A0, A1);
    int i0 = 0;
    while (true) {
        k6_load_group(maskb, lane, i0 + 8, B0, B1);   // prefetch (rows < 2048, padded)
        k6_proc_group(i0, lane, A0, A1, sup0, sup1, val0, val1, count, list);
        i0 += 8;
        if (count >= POST_N || i0 >= PRE_K) break;
        k6_load_group(maskb, lane, i0 + 8, A0, A1);
        k6_proc_group(i0, lane, B0, B1, sup0, sup1, val0, val1, count, list);
        i0 += 8;
        if (count >= POST_N || i0 >= PRE_K) break;
    }
    __syncwarp();

    float* o = out + (size_t)n * POST_N * 5;
    int cmax = count < POST_N ? count : POST_N;
    for (int r = lane; r < POST_N; r += 32) {
        float v0 = 0.f, v1 = 0.f, v2 = 0.f, v3 = 0.f, v4 = 0.f;
        if (r < cmax) {
            int i = list[r];
            float4 b = d_boxes[n * PRE_K + i];
            v0 = b.x; v1 = b.y; v2 = b.z; v3 = b.w;
            v4 = d_selscore[n * PRE_K + i];
        }
        o[r * 5 + 0] = v0;
        o[r * 5 + 1] = v1;
        o[r * 5 + 2] = v2;
        o[r * 5 + 3] = v3;
        o[r * 5 + 4] = v4;
    }
}

// ---------------- launch ----------------
extern "C" void kernel_launch(void* const* d_in, const int* in_sizes, int n_in,
                              void* d_out, int out_size) {
    const float* anchors = (const float*)d_in[0];   // [8, 338688, 4]
    const float* logits  = (const float*)d_in[1];   // [8, 3, 336, 336]
    const float* breg    = (const float*)d_in[2];   // [8, 12, 336, 336]
    float* out = (float*)d_out;                     // [8, 1000, 5]

    (void)in_sizes; (void)n_in; (void)out_size;

    int total = NIMG * MM;
    k0_zero<<<(NIMG * 65536 + 255) / 256, 256>>>();
    k1_scores<<<(total + 255) / 256, 256>>>(logits);
    k2_thresh<<<NIMG, 256>>>();
    k3_compact<<<(total + 255) / 256, 256>>>();
    k4_sortdecode<<<NIMG, 1024>>>(anchors, breg);
    k5_mask<<<NIMG * ((PRE_K + RPB - 1) / RPB), 128>>>();
    k6_nms<<<NIMG, 32>>>(out);
}

// round 5
// speedup vs baseline: 1.6166x; 1.6166x over previous
#include <cuda_runtime.h>
#include <math.h>

#define NIMG 8
#define AA 3
#define HH 336
#define WW 336
#define HWSZ (HH*WW)            // 112896
#define MM (AA*HWSZ)            // 338688
#define PRE_K 2000
#define POST_N 1000
#define CAND_CAP 4096
#define MASK_ROWS 2048
#define MASK_WORDS 64
#define NEGV (-1e9f)
#define FULLM 0xffffffffu
#define GRID_FAT 1184           // 148 SMs * 8 blocks -> one wave at 256 thr

// ---------------- scratch (device globals; no allocations) ----------------
__device__ float              d_scores[NIMG * MM];                       // 10.8 MB (linear order)
__device__ unsigned int       d_hist[NIMG * 65536];                      // 2 MB
__device__ int                d_threshbin[NIMG];
__device__ int                d_candcount[NIMG];
__device__ unsigned long long d_cand[NIMG * CAND_CAP];                   // 256 KB
__device__ float4             d_boxes[NIMG * PRE_K];                     // 256 KB
__device__ float              d_selscore[NIMG * PRE_K];
__device__ float              d_area[NIMG * PRE_K];
__device__ unsigned int       d_maskbits[NIMG * MASK_ROWS * MASK_WORDS]; // 4 MB
__device__ unsigned int       d_validmask[NIMG * MASK_WORDS];

// ---------------- K0: zero counters/hist (grid-stride, one wave) ----------------
__global__ void k0_zero() {
    int stride = gridDim.x * blockDim.x;
    for (int t = blockIdx.x * blockDim.x + threadIdx.x; t < NIMG * 65536; t += stride)
        d_hist[t] = 0u;
    int t0 = blockIdx.x * blockDim.x + threadIdx.x;
    if (t0 < NIMG) d_candcount[t0] = 0;
}

// ---------------- K1: sigmoid + store + ordered histogram (coalesced, 1 wave) ----------------
__global__ void k1_scores(const float* __restrict__ logits) {
    int stride = gridDim.x * blockDim.x;
    for (int t = blockIdx.x * blockDim.x + threadIdx.x; t < NIMG * MM; t += stride) {
        float x = logits[t];                 // linear = fully coalesced
        float s = 1.0f / (1.0f + expf(-x));
        d_scores[t] = s;                     // single source of truth for score bits
        int n = t / MM;
        unsigned u = __float_as_uint(s) | 0x80000000u;  // s >= 0 always
        atomicAdd(&d_hist[(n << 16) + (u >> 16)], 1u);
    }
}

// ---------------- K2: per-image rank-PRE_K threshold bin ----------------
__global__ void k2_thresh() {
    int n = blockIdx.x;
    int t = threadIdx.x;  // 256
    __shared__ unsigned csum[256];
    __shared__ unsigned bins[256];
    __shared__ int      s_chunk;
    __shared__ unsigned s_cum;
    const unsigned* h = d_hist + (n << 16);
    int warp = t >> 5, lane = t & 31;
    for (int c = warp; c < 256; c += 8) {
        unsigned s = 0;
#pragma unroll
        for (int k = 0; k < 8; k++) s += h[c * 256 + lane + k * 32];  // coalesced
#pragma unroll
        for (int o = 16; o; o >>= 1) s += __shfl_down_sync(FULLM, s, o);
        if (lane == 0) csum[c] = s;
    }
    __syncthreads();
    if (t == 0) {
        unsigned cum = 0;
        int chunk = 0;
        for (int c = 255; c >= 0; c--) {
            if (cum + csum[c] >= PRE_K) { chunk = c; break; }
            cum += csum[c];
        }
        s_chunk = chunk;
        s_cum = cum;
    }
    __syncthreads();
    int chunk = s_chunk;
    bins[t] = h[chunk * 256 + t];
    __syncthreads();
    if (t == 0) {
        unsigned cum = s_cum;
        int thresh = chunk * 256;
        for (int b = 255; b >= 0; b--) {
            cum += bins[b];
            if (cum >= PRE_K) { thresh = chunk * 256 + b; break; }
        }
        d_threshbin[n] = thresh;
    }
}

// ---------------- K3: compact candidate keys (reads stored scores; 1 wave) ----------------
__global__ void k3_compact() {
    int stride = gridDim.x * blockDim.x;
    for (int t = blockIdx.x * blockDim.x + threadIdx.x; t < NIMG * MM; t += stride) {
        float s = d_scores[t];               // identical bits to k1 by construction
        int n = t / MM;
        int rem = t - n * MM;
        unsigned u = __float_as_uint(s) | 0x80000000u;
        if ((int)(u >> 16) >= d_threshbin[n]) {
            int a  = rem / HWSZ;
            int hw = rem - a * HWSZ;
            unsigned f = (unsigned)(hw * AA + a);   // score-order index
            int pos = atomicAdd(&d_candcount[n], 1);
            if (pos < CAND_CAP) {
                d_cand[n * CAND_CAP + pos] =
                    ((unsigned long long)u << 32) | (unsigned long long)(0xFFFFFFFFu - f);
            }
        }
    }
}

// ---------------- K4: bitonic sort (full block syncs) + decode top-2000 ----------------
__global__ __launch_bounds__(1024) void k4_sortdecode(const float* __restrict__ anchors,
                                                      const float* __restrict__ breg) {
    __shared__ unsigned long long sm[CAND_CAP];
    int n = blockIdx.x;
    int tid = threadIdx.x;  // 1024
    int cnt = d_candcount[n];
    if (cnt > CAND_CAP) cnt = CAND_CAP;
    for (int i = tid; i < CAND_CAP; i += 1024)
        sm[i] = (i < cnt) ? d_cand[n * CAND_CAP + i] : 0ULL;
    __syncthreads();

    // bitonic sort, descending — __syncthreads after every substage (proven replay-safe)
    for (int k = 2; k <= CAND_CAP; k <<= 1) {
        for (int j = k >> 1; j > 0; j >>= 1) {
#pragma unroll
            for (int t4 = 0; t4 < CAND_CAP / 1024; t4++) {
                int i = tid + t4 * 1024;
                int ixj = i ^ j;
                if (ixj > i) {
                    unsigned long long va = sm[i], vb = sm[ixj];
                    bool desc = ((i & k) == 0);
                    if (desc ? (va < vb) : (va > vb)) { sm[i] = vb; sm[ixj] = va; }
                }
            }
            __syncthreads();
        }
    }

    const float XCLIP = 4.135166556742356f;  // log(1000/16)
#pragma unroll
    for (int pass = 0; pass < 2; pass++) {
        int r = tid + pass * 1024;
        bool keepf = false;
        if (r < PRE_K) {
            unsigned long long key = sm[r];
            unsigned ub = (unsigned)(key >> 32);
            unsigned sbits = (ub & 0x80000000u) ? (ub ^ 0x80000000u) : ~ub;
            float s = __uint_as_float(sbits);
            unsigned f = 0xFFFFFFFFu - (unsigned)(key & 0xFFFFFFFFull);
            int a  = (int)(f % AA);
            int hw = (int)(f / AA);
            float4 anc = ((const float4*)anchors)[(size_t)n * MM + f];
            const float* rp = breg + ((size_t)n * (AA * 4) + a * 4) * HWSZ + hw;
            float dx = rp[0];
            float dy = rp[HWSZ];
            float dwv = rp[2 * HWSZ];
            float dhv = rp[3 * HWSZ];
            float aw = __fadd_rn(__fsub_rn(anc.z, anc.x), 1.0f);
            float ah = __fadd_rn(__fsub_rn(anc.w, anc.y), 1.0f);
            float cx = __fadd_rn(anc.x, __fmul_rn(0.5f, aw));
            float cy = __fadd_rn(anc.y, __fmul_rn(0.5f, ah));
            dwv = fminf(dwv, XCLIP);
            dhv = fminf(dhv, XCLIP);
            float pcx = __fadd_rn(__fmul_rn(dx, aw), cx);
            float pcy = __fadd_rn(__fmul_rn(dy, ah), cy);
            float pw = __fmul_rn((float)exp((double)dwv), aw);
            float ph = __fmul_rn((float)exp((double)dhv), ah);
            float hpw = __fmul_rn(0.5f, pw);
            float hph = __fmul_rn(0.5f, ph);
            float x1 = __fsub_rn(pcx, hpw);
            float y1 = __fsub_rn(pcy, hph);
            float x2 = __fsub_rn(__fadd_rn(pcx, hpw), 1.0f);
            float y2 = __fsub_rn(__fadd_rn(pcy, hph), 1.0f);
            x1 = fminf(fmaxf(x1, 0.0f), 1332.0f);
            x2 = fminf(fmaxf(x2, 0.0f), 1332.0f);
            y1 = fminf(fmaxf(y1, 0.0f), 799.0f);
            y2 = fminf(fmaxf(y2, 0.0f), 799.0f);
            float ws = __fadd_rn(__fsub_rn(x2, x1), 1.0f);
            float hs = __fadd_rn(__fsub_rn(y2, y1), 1.0f);
            keepf = (ws >= 0.0f) && (hs >= 0.0f);
            d_boxes[n * PRE_K + r] = make_float4(x1, y1, x2, y2);
            d_area[n * PRE_K + r] = __fmul_rn(ws, hs);
            d_selscore[n * PRE_K + r] = keepf ? s : NEGV;
        }
        unsigned bal = __ballot_sync(FULLM, keepf);
        if ((tid & 31) == 0) d_validmask[n * MASK_WORDS + (r >> 5)] = bal;
    }
}

// ---------------- K5: 2000x2000 suppression bitmask (reg-resident row tiles, no div) ----------------
#define RPB 32
__global__ __launch_bounds__(128) void k5_mask() {
    __shared__ float4 sb[2048];
    __shared__ float  sa[2048];
    const int bpi = (PRE_K + RPB - 1) / RPB;  // 63
    int n  = blockIdx.x / bpi;
    int rb = (blockIdx.x % bpi) * RPB;
    int tid = threadIdx.x;  // 128
    for (int i = tid; i < 2048; i += 128) {
        if (i < PRE_K) { sb[i] = d_boxes[n * PRE_K + i]; sa[i] = d_area[n * PRE_K + i]; }
        else           { sb[i] = make_float4(0.f, 0.f, -1.f, -1.f); sa[i] = 1.0f; }
    }
    __syncthreads();
    int warp = tid >> 5, lane = tid & 31;
    int r0 = rb + warp * 8;
    if (r0 >= PRE_K) return;   // whole-warp tail (no further block sync)

    float4 bi[8]; float ai[8];
#pragma unroll
    for (int d = 0; d < 8; d++) { bi[d] = sb[r0 + d]; ai[d] = sa[r0 + d]; }
    unsigned* rowbase = d_maskbits + ((size_t)n * MASK_ROWS + r0) * MASK_WORDS;

    // iou > 0.7  <=>  inter > (0.7/1.7)*(ai+aj)   (areas >= 0 => denom > 0)
    // guard band +-~0.06%; ambiguous pairs fall back to the exact division.
    const float HIC = 0.41200f, LOC = 0.41153f;
    for (int w = 0; w < 64; w++) {
        int j = (w << 5) + lane;
        float4 bj = sb[j];
        float  aj = sa[j];
        unsigned words[8];
#pragma unroll
        for (int d = 0; d < 8; d++) {
            float xx1 = fmaxf(bi[d].x, bj.x);
            float yy1 = fmaxf(bi[d].y, bj.y);
            float xx2 = fminf(bi[d].z, bj.z);
            float yy2 = fminf(bi[d].w, bj.w);
            float iw = fmaxf(__fadd_rn(__fsub_rn(xx2, xx1), 1.0f), 0.0f);
            float ih = fmaxf(__fadd_rn(__fsub_rn(yy2, yy1), 1.0f), 0.0f);
            float inter = __fmul_rn(iw, ih);
            float ssum  = __fadd_rn(ai[d], aj);
            bool sup;
            if (inter > __fmul_rn(HIC, ssum))      sup = true;
            else if (inter < __fmul_rn(LOC, ssum)) sup = false;
            else sup = __fdiv_rn(inter, __fsub_rn(ssum, inter)) > 0.7f;
            words[d] = __ballot_sync(FULLM, sup);
        }
        if (lane == 0) {
#pragma unroll
            for (int d = 0; d < 8; d++) rowbase[(size_t)d * MASK_WORDS + w] = words[d];
        }
    }
}

// ---------------- K6: serial greedy NMS scan, 1 warp per image ----------------
__device__ __forceinline__ void k6_load_group(const unsigned* __restrict__ maskb, int lane,
                                              int i0, unsigned (&b0)[8], unsigned (&b1)[8]) {
#pragma unroll
    for (int d = 0; d < 8; d++) {
        const unsigned* r = maskb + (size_t)(i0 + d) * MASK_WORDS;
        b0[d] = r[lane];
        b1[d] = r[lane + 32];
    }
}

__device__ __forceinline__ void k6_proc_group(int i0, int lane,
                                              unsigned (&b0)[8], unsigned (&b1)[8],
                                              unsigned& sup0, unsigned& sup1,
                                              unsigned val0, unsigned val1,
                                              int& count, int* list) {
    int Wd = i0 >> 5;             // constant across the 8-row group
    int slot = Wd >> 5;
    int ol = Wd & 31;
    unsigned kb = slot ? sup1 : sup0;
    unsigned kv = slot ? val1 : val0;
    unsigned keep8 = 0;
    int bit0 = i0 & 31;
#pragma unroll
    for (int d = 0; d < 8; d++) {
        unsigned m = 1u << (bit0 + d);
        if ((kv & m) && !(kb & m)) {
            keep8 |= (1u << d);
            kb |= slot ? b1[d] : b0[d];   // owner lane holds word Wd of row i0+d
        }
    }
    keep8 = __shfl_sync(FULLM, keep8, ol);
#pragma unroll
    for (int d = 0; d < 8; d++) {
        if (keep8 & (1u << d)) { sup0 |= b0[d]; sup1 |= b1[d]; }
    }
    if (lane == 0) {
        int c = count;
#pragma unroll
        for (int d = 0; d < 8; d++) {
            if (keep8 & (1u << d)) {
                if (c < POST_N) list[c] = i0 + d;
                c++;
            }
        }
    }
    count += __popc(keep8);
}

__global__ __launch_bounds__(32) void k6_nms(float* __restrict__ out) {
    int n = blockIdx.x;
    int lane = threadIdx.x;
    __shared__ int list[POST_N];
    const unsigned* maskb = d_maskbits + (size_t)n * MASK_ROWS * MASK_WORDS;
    unsigned sup0 = 0, sup1 = 0;
    unsigned val0 = d_validmask[n * MASK_WORDS + lane];
    unsigned val1 = d_validmask[n * MASK_WORDS + 32 + lane];
    int count = 0;
    unsigned A0[8], A1[8], B0[8], B1[8];

    k6_load_group(maskb, lane, 0, A0, A1);
    int i0 = 0;
    while (true) {
        k6_load_group(maskb, lane, i0 + 8, B0, B1);   // prefetch (rows < 2048, padded)
        k6_proc_group(i0, lane, A0, A1, sup0, sup1, val0, val1, count, list);
        i0 += 8;
        if (count >= POST_N || i0 >= PRE_K) break;
        k6_load_group(maskb, lane, i0 + 8, A0, A1);
        k6_proc_group(i0, lane, B0, B1, sup0, sup1, val0, val1, count, list);
        i0 += 8;
        if (count >= POST_N || i0 >= PRE_K) break;
    }
    __syncwarp();

    float* o = out + (size_t)n * POST_N * 5;
    int cmax = count < POST_N ? count : POST_N;
    for (int r = lane; r < POST_N; r += 32) {
        float v0 = 0.f, v1 = 0.f, v2 = 0.f, v3 = 0.f, v4 = 0.f;
        if (r < cmax) {
            int i = list[r];
            float4 b = d_boxes[n * PRE_K + i];
            v0 = b.x; v1 = b.y; v2 = b.z; v3 = b.w;
            v4 = d_selscore[n * PRE_K + i];
        }
        o[r * 5 + 0] = v0;
        o[r * 5 + 1] = v1;
        o[r * 5 + 2] = v2;
        o[r * 5 + 3] = v3;
        o[r * 5 + 4] = v4;
    }
}

// ---------------- launch ----------------
extern "C" void kernel_launch(void* const* d_in, const int* in_sizes, int n_in,
                              void* d_out, int out_size) {
    const float* anchors = (const float*)d_in[0];   // [8, 338688, 4]
    const float* logits  = (const float*)d_in[1];   // [8, 3, 336, 336]
    const float* breg    = (const float*)d_in[2];   // [8, 12, 336, 336]
    float* out = (float*)d_out;                     // [8, 1000, 5]

    (void)in_sizes; (void)n_in; (void)out_size;

    k0_zero<<<GRID_FAT, 256>>>();
    k1_scores<<<GRID_FAT, 256>>>(logits);
    k2_thresh<<<NIMG, 256>>>();
    k3_compact<<<GRID_FAT, 256>>>();
    k4_sortdecode<<<NIMG, 1024>>>(anchors, breg);
    k5_mask<<<NIMG * ((PRE_K + RPB - 1) / RPB), 128>>>();
    k6_nms<<<NIMG, 32>>>(out);
}